// round 1
// baseline (speedup 1.0000x reference)
#include <cuda_runtime.h>
#include <cuda_bf16.h>
#include <math.h>

#define NN   50000
#define HID  64
#define N2V  64
#define EE   800000
#define EP   100000
#define LYR  2
#define BN_EPS 1e-5f

// ---------------- scratch (no allocation allowed) ----------------
__device__ float g_x[NN * HID];
__device__ float g_h[NN * HID];
__device__ float g_agg[NN * HID];
__device__ float g_dis[NN];
__device__ int   g_deg[NN];
__device__ float g_stats[2 * HID];   // [0:64) sum, [64:128) sumsq
__device__ float g_scale[HID];
__device__ float g_shift[HID];

// ---------------- degree / norm ----------------
__global__ void k_deg_init() {
    int n = blockIdx.x * blockDim.x + threadIdx.x;
    if (n < NN) g_deg[n] = 1;   // self-loop
}

__global__ void k_deg_count(const int* __restrict__ ei) {
    int e = blockIdx.x * blockDim.x + threadIdx.x;
    if (e < EE) atomicAdd(&g_deg[ei[EE + e]], 1);   // col = destination
}

__global__ void k_dis() {
    int n = blockIdx.x * blockDim.x + threadIdx.x;
    if (n < NN) g_dis[n] = rsqrtf((float)g_deg[n]);
}

// ---------------- input projection: x = [id|n2v] @ W + b ----------------
// block: 256 threads, 32 nodes. Smem: W 128x64 (32KB) + rows 32x128 (16KB) = 48KB
__global__ void k_proj(const float* __restrict__ id_emb,
                       const float* __restrict__ n2v_emb,
                       const float* __restrict__ W,
                       const float* __restrict__ b) {
    __shared__ float Ws[128 * 64];
    __shared__ float Xs[32 * 128];
    int tid = threadIdx.x;
    int base = blockIdx.x * 32;

    for (int i = tid; i < 128 * 64; i += 256) Ws[i] = W[i];
    for (int i = tid; i < 32 * 128; i += 256) {
        int node = i >> 7, k = i & 127;
        int gn = base + node;
        float v = 0.f;
        if (gn < NN) v = (k < 64) ? id_emb[gn * 64 + k] : n2v_emb[gn * 64 + (k - 64)];
        Xs[i] = v;
    }
    __syncthreads();

    int c = tid & 63, g = tid >> 6;            // column, node-group (4 groups x 8 nodes)
    float acc[8];
#pragma unroll
    for (int i = 0; i < 8; i++) acc[i] = 0.f;
    for (int k = 0; k < 128; k++) {
        float wv = Ws[k * 64 + c];
#pragma unroll
        for (int i = 0; i < 8; i++) acc[i] += Xs[(g * 8 + i) * 128 + k] * wv;
    }
    float bv = b[c];
#pragma unroll
    for (int i = 0; i < 8; i++) {
        int gn = base + g * 8 + i;
        if (gn < NN) g_x[gn * 64 + c] = acc[i] + bv;
    }
}

// ---------------- conv GEMM: h = x @ W[l]  (K = 64) ----------------
__global__ void k_gemm64(const float* __restrict__ W) {
    __shared__ float Ws[64 * 64];
    __shared__ float Xs[32 * 64];
    int tid = threadIdx.x;
    int base = blockIdx.x * 32;

    for (int i = tid; i < 64 * 64; i += 256) Ws[i] = W[i];
    for (int i = tid; i < 32 * 64; i += 256) {
        int gn = base + (i >> 6);
        Xs[i] = (gn < NN) ? g_x[gn * 64 + (i & 63)] : 0.f;
    }
    __syncthreads();

    int c = tid & 63, g = tid >> 6;
    float acc[8];
#pragma unroll
    for (int i = 0; i < 8; i++) acc[i] = 0.f;
#pragma unroll 4
    for (int k = 0; k < 64; k++) {
        float wv = Ws[k * 64 + c];
#pragma unroll
        for (int i = 0; i < 8; i++) acc[i] += Xs[(g * 8 + i) * 64 + k] * wv;
    }
#pragma unroll
    for (int i = 0; i < 8; i++) {
        int gn = base + g * 8 + i;
        if (gn < NN) g_h[gn * 64 + c] = acc[i];
    }
}

// ---------------- agg init: conv bias + self-loop term ----------------
__global__ void k_agg_init(const float* __restrict__ conv_b) {
    int i = blockIdx.x * blockDim.x + threadIdx.x;
    if (i < NN * 64) {
        int n = i >> 6, c = i & 63;
        float d = g_dis[n];
        g_agg[i] = conv_b[c] + g_h[i] * d * d;    // self-loop norm = dis[n]^2
    }
}

// ---------------- edge scatter: agg[col] += dis[row]*dis[col] * h[row] ----------------
// 16 threads per edge, one float4 REDG each.
__global__ void k_scatter(const int* __restrict__ ei) {
    unsigned t = blockIdx.x * blockDim.x + threadIdx.x;
    int e = (int)(t >> 4);
    int l = (int)(t & 15);
    if (e >= EE) return;
    int r = __ldg(ei + e);
    int c = __ldg(ei + EE + e);
    float w = __ldg(g_dis + r) * __ldg(g_dis + c);
    float4 hv = __ldg(reinterpret_cast<const float4*>(g_h + r * 64) + l);
    float4* dst = reinterpret_cast<float4*>(g_agg + c * 64) + l;
    asm volatile("red.global.add.v4.f32 [%0], {%1,%2,%3,%4};"
                 :: "l"(dst), "f"(hv.x * w), "f"(hv.y * w), "f"(hv.z * w), "f"(hv.w * w)
                 : "memory");
}

// ---------------- BatchNorm ----------------
__global__ void k_zero_stats() {
    int i = threadIdx.x;
    if (i < 2 * HID) g_stats[i] = 0.f;
}

__global__ void k_bn_reduce() {
    __shared__ float sh_s[256];
    __shared__ float sh_q[256];
    int tid = threadIdx.x;
    int c = tid & 63, g = tid >> 6;
    float s = 0.f, q = 0.f;
    for (int n = blockIdx.x * 4 + g; n < NN; n += gridDim.x * 4) {
        float v = g_agg[n * 64 + c];
        s += v; q += v * v;
    }
    sh_s[tid] = s; sh_q[tid] = q;
    __syncthreads();
    if (tid < 64) {
        s = sh_s[tid] + sh_s[tid + 64] + sh_s[tid + 128] + sh_s[tid + 192];
        q = sh_q[tid] + sh_q[tid + 64] + sh_q[tid + 128] + sh_q[tid + 192];
        atomicAdd(&g_stats[tid], s);
        atomicAdd(&g_stats[64 + tid], q);
    }
}

__global__ void k_bn_finalize(const float* __restrict__ gamma,
                              const float* __restrict__ beta) {
    int c = threadIdx.x;
    if (c < 64) {
        float mu  = g_stats[c] * (1.0f / NN);
        float var = g_stats[64 + c] * (1.0f / NN) - mu * mu;
        float inv = rsqrtf(var + BN_EPS);
        float gm  = gamma[c];
        g_scale[c] = gm * inv;
        g_shift[c] = beta[c] - mu * inv * gm;
    }
}

__global__ void k_bn_apply() {
    int i = blockIdx.x * blockDim.x + threadIdx.x;
    if (i < NN * 64) {
        int c = i & 63;
        float v = g_agg[i] * g_scale[c] + g_shift[c];
        g_x[i] += fmaxf(v, 0.f);
    }
}

// ---------------- link decoder ----------------
__global__ void k_decode(const int* __restrict__ pe, float* __restrict__ out) {
    int w = (blockIdx.x * blockDim.x + threadIdx.x) >> 5;
    int lane = threadIdx.x & 31;
    if (w >= EP) return;
    int a = __ldg(pe + 2 * w);
    int b = __ldg(pe + 2 * w + 1);
    float2 za = __ldg(reinterpret_cast<const float2*>(g_x + a * 64) + lane);
    float2 zb = __ldg(reinterpret_cast<const float2*>(g_x + b * 64) + lane);
    float s = za.x * zb.x + za.y * zb.y;
#pragma unroll
    for (int o = 16; o; o >>= 1) s += __shfl_xor_sync(0xffffffffu, s, o);
    if (lane == 0) out[w] = s;
}

// ---------------- launch ----------------
extern "C" void kernel_launch(void* const* d_in, const int* in_sizes, int n_in,
                              void* d_out, int out_size) {
    const int*   edge_index = (const int*)d_in[0];   // (2, E)
    const int*   pred_edge  = (const int*)d_in[1];   // (EP, 2)
    const float* id_emb     = (const float*)d_in[2]; // (N, 64)
    const float* n2v_emb    = (const float*)d_in[3]; // (N, 64)
    const float* proj_w     = (const float*)d_in[4]; // (128, 64)
    const float* proj_b     = (const float*)d_in[5]; // (64,)
    const float* conv_w     = (const float*)d_in[6]; // (2, 64, 64)
    const float* conv_b     = (const float*)d_in[7]; // (2, 64)
    const float* bn_gamma   = (const float*)d_in[8]; // (2, 64)
    const float* bn_beta    = (const float*)d_in[9]; // (2, 64)
    float*       out        = (float*)d_out;         // (EP,)

    const int TB = 256;

    // degrees + symmetric norm
    k_deg_init <<<(NN + TB - 1) / TB, TB>>>();
    k_deg_count<<<(EE + TB - 1) / TB, TB>>>(edge_index);
    k_dis      <<<(NN + TB - 1) / TB, TB>>>();

    // input projection
    k_proj<<<(NN + 31) / 32, TB>>>(id_emb, n2v_emb, proj_w, proj_b);

    for (int l = 0; l < LYR; l++) {
        k_gemm64  <<<(NN + 31) / 32, TB>>>(conv_w + l * HID * HID);
        k_agg_init<<<(NN * HID + TB - 1) / TB, TB>>>(conv_b + l * HID);
        k_scatter <<<(EE * 16 + TB - 1) / TB, TB>>>(edge_index);
        k_zero_stats<<<1, 128>>>();
        k_bn_reduce<<<256, TB>>>();
        k_bn_finalize<<<1, 64>>>(bn_gamma + l * HID, bn_beta + l * HID);
        k_bn_apply<<<(NN * HID + TB - 1) / TB, TB>>>();
    }

    k_decode<<<(EP * 32 + TB - 1) / TB, TB>>>(pred_edge, out);
}

// round 3
// speedup vs baseline: 1.3361x; 1.3361x over previous
#include <cuda_runtime.h>
#include <cuda_bf16.h>
#include <math.h>

#define NN   50000
#define HID  64
#define EE   800000
#define EP   100000
#define LYR  2
#define BN_EPS 1e-5f

// ---------------- scratch ----------------
__device__ float g_x[NN * HID];
__device__ float g_h[NN * HID];
__device__ float g_agg[NN * HID];
__device__ float g_dis[NN];
__device__ int   g_deg[NN];
__device__ float g_stats[2 * HID];   // [0:64) sum, [64:128) sumsq

// ---------------- degree / norm ----------------
__global__ void k_deg_init() {
    int n = blockIdx.x * blockDim.x + threadIdx.x;
    if (n < NN) g_deg[n] = 1;   // self-loop
}

__global__ void k_deg_count(const int* __restrict__ ei) {
    int e = blockIdx.x * blockDim.x + threadIdx.x;
    if (e < EE) atomicAdd(&g_deg[ei[EE + e]], 1);
}

__global__ void k_dis() {
    int n = blockIdx.x * blockDim.x + threadIdx.x;
    if (n < NN) g_dis[n] = rsqrtf((float)g_deg[n]);
}

// ============ register-tiled GEMM helpers ============
// Block tile: 64 nodes x 64 cols, 256 threads, thread tile 4x4.
// Per 4-k step: 8 x LDS.128 -> 64 FMA.

__device__ __forceinline__ void load_tile64(float* Xs, const float* __restrict__ src,
                                            int base, int tid) {
    // load 64 rows x 64 cols from src[node*64 + k], rows >= NN zeroed
    for (int j = tid; j < 1024; j += 256) {
        int n = j >> 4;            // 4 float4 per row
        int gn = base + n;
        float4 v = make_float4(0.f, 0.f, 0.f, 0.f);
        if (gn < NN) v = *reinterpret_cast<const float4*>(src + gn * 64 + (j & 15) * 4);
        *reinterpret_cast<float4*>(Xs + j * 4) = v;
    }
}

__device__ __forceinline__ void mm_accum(const float* Xs, const float* Ws,
                                         int n0, int c0, float4 acc[4]) {
#pragma unroll
    for (int k = 0; k < 64; k += 4) {
        float4 wv0 = *reinterpret_cast<const float4*>(Ws + (k + 0) * 64 + c0);
        float4 wv1 = *reinterpret_cast<const float4*>(Ws + (k + 1) * 64 + c0);
        float4 wv2 = *reinterpret_cast<const float4*>(Ws + (k + 2) * 64 + c0);
        float4 wv3 = *reinterpret_cast<const float4*>(Ws + (k + 3) * 64 + c0);
#pragma unroll
        for (int i = 0; i < 4; i++) {
            float4 xv = *reinterpret_cast<const float4*>(Xs + (n0 + i) * 64 + k);
            acc[i].x += xv.x * wv0.x + xv.y * wv1.x + xv.z * wv2.x + xv.w * wv3.x;
            acc[i].y += xv.x * wv0.y + xv.y * wv1.y + xv.z * wv2.y + xv.w * wv3.y;
            acc[i].z += xv.x * wv0.z + xv.y * wv1.z + xv.z * wv2.z + xv.w * wv3.z;
            acc[i].w += xv.x * wv0.w + xv.y * wv1.w + xv.z * wv2.w + xv.w * wv3.w;
        }
    }
}

// ---------------- input projection: x = [id|n2v] @ W + b (two 64-chunks) --------
__global__ __launch_bounds__(256) void k_proj(const float* __restrict__ id_emb,
                                              const float* __restrict__ n2v_emb,
                                              const float* __restrict__ W,
                                              const float* __restrict__ b) {
    __shared__ float Xs[64 * 64];
    __shared__ float Ws[64 * 64];
    int tid = threadIdx.x;
    int base = blockIdx.x * 64;
    int cg = tid & 15, ng = tid >> 4;
    int c0 = cg * 4, n0 = ng * 4;

    float4 acc[4];
#pragma unroll
    for (int i = 0; i < 4; i++) acc[i] = make_float4(0.f, 0.f, 0.f, 0.f);

#pragma unroll
    for (int chunk = 0; chunk < 2; chunk++) {
        const float* src = chunk ? n2v_emb : id_emb;
        const float* Wsrc = W + chunk * 64 * 64;
        load_tile64(Xs, src, base, tid);
        for (int j = tid; j < 1024; j += 256)
            *reinterpret_cast<float4*>(Ws + j * 4) =
                *reinterpret_cast<const float4*>(Wsrc + j * 4);
        __syncthreads();
        mm_accum(Xs, Ws, n0, c0, acc);
        __syncthreads();
    }

    float4 b4 = *reinterpret_cast<const float4*>(b + c0);
#pragma unroll
    for (int i = 0; i < 4; i++) {
        int gn = base + n0 + i;
        if (gn < NN) {
            float4 o = make_float4(acc[i].x + b4.x, acc[i].y + b4.y,
                                   acc[i].z + b4.z, acc[i].w + b4.w);
            *reinterpret_cast<float4*>(g_x + gn * 64 + c0) = o;
        }
    }
}

// ---------------- conv GEMM fused with agg init + stats zero ----------------
// h = x @ W;  agg = conv_b + h * dis^2 (self-loop term)
__global__ __launch_bounds__(256) void k_conv(const float* __restrict__ W,
                                              const float* __restrict__ conv_b) {
    __shared__ float Xs[64 * 64];
    __shared__ float Ws[64 * 64];
    int tid = threadIdx.x;
    int base = blockIdx.x * 64;
    int cg = tid & 15, ng = tid >> 4;
    int c0 = cg * 4, n0 = ng * 4;

    if (blockIdx.x == 0 && tid < 128) g_stats[tid] = 0.f;   // zero BN stats

    load_tile64(Xs, g_x, base, tid);
    for (int j = tid; j < 1024; j += 256)
        *reinterpret_cast<float4*>(Ws + j * 4) =
            *reinterpret_cast<const float4*>(W + j * 4);
    __syncthreads();

    float4 acc[4];
#pragma unroll
    for (int i = 0; i < 4; i++) acc[i] = make_float4(0.f, 0.f, 0.f, 0.f);
    mm_accum(Xs, Ws, n0, c0, acc);

    float4 b4 = *reinterpret_cast<const float4*>(conv_b + c0);
#pragma unroll
    for (int i = 0; i < 4; i++) {
        int gn = base + n0 + i;
        if (gn < NN) {
            *reinterpret_cast<float4*>(g_h + gn * 64 + c0) = acc[i];
            float d = g_dis[gn];
            float w = d * d;
            float4 a = make_float4(acc[i].x * w + b4.x, acc[i].y * w + b4.y,
                                   acc[i].z * w + b4.z, acc[i].w * w + b4.w);
            *reinterpret_cast<float4*>(g_agg + gn * 64 + c0) = a;
        }
    }
}

// ---------------- edge scatter: agg[col] += dis[row]*dis[col] * h[row] ----------
__global__ void k_scatter(const int* __restrict__ ei) {
    unsigned t = blockIdx.x * blockDim.x + threadIdx.x;
    int e = (int)(t >> 4);
    int l = (int)(t & 15);
    if (e >= EE) return;
    int r = __ldg(ei + e);
    int c = __ldg(ei + EE + e);
    float w = __ldg(g_dis + r) * __ldg(g_dis + c);
    float4 hv = __ldg(reinterpret_cast<const float4*>(g_h + r * 64) + l);
    float4* dst = reinterpret_cast<float4*>(g_agg + c * 64) + l;
    asm volatile("red.global.add.v4.f32 [%0], {%1,%2,%3,%4};"
                 :: "l"(dst), "f"(hv.x * w), "f"(hv.y * w), "f"(hv.z * w), "f"(hv.w * w)
                 : "memory");
}

// ---------------- BatchNorm reduce ----------------
__global__ void k_bn_reduce() {
    __shared__ float sh_s[256];
    __shared__ float sh_q[256];
    int tid = threadIdx.x;
    int c = tid & 63, g = tid >> 6;
    float s = 0.f, q = 0.f;
    for (int n = blockIdx.x * 4 + g; n < NN; n += gridDim.x * 4) {
        float v = g_agg[n * 64 + c];
        s += v; q += v * v;
    }
    sh_s[tid] = s; sh_q[tid] = q;
    __syncthreads();
    if (tid < 64) {
        s = sh_s[tid] + sh_s[tid + 64] + sh_s[tid + 128] + sh_s[tid + 192];
        q = sh_q[tid] + sh_q[tid + 64] + sh_q[tid + 128] + sh_q[tid + 192];
        atomicAdd(&g_stats[tid], s);
        atomicAdd(&g_stats[64 + tid], q);
    }
}

// ---------------- BN finalize + apply + residual relu (fused) ----------------
__global__ void k_bn_apply(const float* __restrict__ gamma,
                           const float* __restrict__ beta) {
    __shared__ float sc[64], sf[64];
    int tid = threadIdx.x;
    if (tid < 64) {
        float mu  = g_stats[tid] * (1.0f / NN);
        float var = g_stats[64 + tid] * (1.0f / NN) - mu * mu;
        float inv = rsqrtf(var + BN_EPS);
        float gm  = gamma[tid];
        sc[tid] = gm * inv;
        sf[tid] = beta[tid] - mu * inv * gm;
    }
    __syncthreads();
    int i = blockIdx.x * blockDim.x + tid;          // float4 index
    if (i < NN * 16) {
        int c0 = (i & 15) * 4;
        float4 v = reinterpret_cast<const float4*>(g_agg)[i];
        float4 x = reinterpret_cast<const float4*>(g_x)[i];
        x.x += fmaxf(v.x * sc[c0 + 0] + sf[c0 + 0], 0.f);
        x.y += fmaxf(v.y * sc[c0 + 1] + sf[c0 + 1], 0.f);
        x.z += fmaxf(v.z * sc[c0 + 2] + sf[c0 + 2], 0.f);
        x.w += fmaxf(v.w * sc[c0 + 3] + sf[c0 + 3], 0.f);
        reinterpret_cast<float4*>(g_x)[i] = x;
    }
}

// ---------------- link decoder ----------------
__global__ void k_decode(const int* __restrict__ pe, float* __restrict__ out) {
    int w = (blockIdx.x * blockDim.x + threadIdx.x) >> 5;
    int lane = threadIdx.x & 31;
    if (w >= EP) return;
    int a = __ldg(pe + 2 * w);
    int b = __ldg(pe + 2 * w + 1);
    float2 za = __ldg(reinterpret_cast<const float2*>(g_x + a * 64) + lane);
    float2 zb = __ldg(reinterpret_cast<const float2*>(g_x + b * 64) + lane);
    float s = za.x * zb.x + za.y * zb.y;
#pragma unroll
    for (int o = 16; o; o >>= 1) s += __shfl_xor_sync(0xffffffffu, s, o);
    if (lane == 0) out[w] = s;
}

// ---------------- launch ----------------
extern "C" void kernel_launch(void* const* d_in, const int* in_sizes, int n_in,
                              void* d_out, int out_size) {
    const int*   edge_index = (const int*)d_in[0];
    const int*   pred_edge  = (const int*)d_in[1];
    const float* id_emb     = (const float*)d_in[2];
    const float* n2v_emb    = (const float*)d_in[3];
    const float* proj_w     = (const float*)d_in[4];
    const float* proj_b     = (const float*)d_in[5];
    const float* conv_w     = (const float*)d_in[6];
    const float* conv_b     = (const float*)d_in[7];
    const float* bn_gamma   = (const float*)d_in[8];
    const float* bn_beta    = (const float*)d_in[9];
    float*       out        = (float*)d_out;

    const int TB = 256;
    const int GBLK = (NN + 63) / 64;

    k_deg_init <<<(NN + TB - 1) / TB, TB>>>();
    k_deg_count<<<(EE + TB - 1) / TB, TB>>>(edge_index);
    k_dis      <<<(NN + TB - 1) / TB, TB>>>();

    k_proj<<<GBLK, TB>>>(id_emb, n2v_emb, proj_w, proj_b);

    for (int l = 0; l < LYR; l++) {
        k_conv   <<<GBLK, TB>>>(conv_w + l * HID * HID, conv_b + l * HID);
        k_scatter<<<(EE * 16 + TB - 1) / TB, TB>>>(edge_index);
        k_bn_reduce<<<256, TB>>>();
        k_bn_apply<<<(NN * 16 + TB - 1) / TB, TB>>>(bn_gamma + l * HID, bn_beta + l * HID);
    }

    k_decode<<<(EP * 32 + TB - 1) / TB, TB>>>(pred_edge, out);
}

// round 4
// speedup vs baseline: 1.4902x; 1.1154x over previous
#include <cuda_runtime.h>
#include <cuda_bf16.h>
#include <math.h>

#define NN   50000
#define HID  64
#define EE   800000
#define EP   100000
#define LYR  2
#define BN_EPS 1e-5f
#define NB_SCAN 196            // 196 * 256 = 50176 >= NN

// ---------------- scratch ----------------
__device__ float g_x[NN * HID];
__device__ float g_h[NN * HID];
__device__ float g_agg[NN * HID];
__device__ float g_dis[NN];
__device__ int   g_deg[NN];
__device__ int   g_cnt[NN];
__device__ int   g_row_start[NN + 1];
__device__ int   g_csr_src[EE];
__device__ float g_csr_w[EE];
__device__ int   g_part[256];
__device__ float g_stats[2 * HID];   // [0:64) sum, [64:128) sumsq

// ---------------- degree / norm / CSR build ----------------
__global__ void k_init() {
    int n = blockIdx.x * blockDim.x + threadIdx.x;
    if (n < NN) { g_deg[n] = 1; g_cnt[n] = 0; }   // deg includes self-loop
    if (n == 0) g_row_start[NN] = EE;
}

__global__ void k_deg_count(const int* __restrict__ ei) {
    int e = blockIdx.x * blockDim.x + threadIdx.x;
    if (e < EE) atomicAdd(&g_deg[ei[EE + e]], 1);
}

__global__ void k_dis() {
    int n = blockIdx.x * blockDim.x + threadIdx.x;
    if (n < NN) g_dis[n] = rsqrtf((float)g_deg[n]);
}

// block partial sums of (deg-1)
__global__ void k_scan_part() {
    __shared__ int sh[256];
    int t = threadIdx.x;
    int idx = blockIdx.x * 256 + t;
    sh[t] = (idx < NN) ? g_deg[idx] - 1 : 0;
    __syncthreads();
    for (int o = 128; o > 0; o >>= 1) {
        if (t < o) sh[t] += sh[t + o];
        __syncthreads();
    }
    if (t == 0) g_part[blockIdx.x] = sh[0];
}

// exclusive scan of block partials
__global__ void k_scan_mid() {
    __shared__ int sh[256];
    int t = threadIdx.x;
    int v = (t < NB_SCAN) ? g_part[t] : 0;
    sh[t] = v;
    __syncthreads();
    for (int o = 1; o < 256; o <<= 1) {
        int s = (t >= o) ? sh[t - o] : 0;
        __syncthreads();
        sh[t] += s;
        __syncthreads();
    }
    if (t < NB_SCAN) g_part[t] = sh[t] - v;   // exclusive
}

// per-element exclusive scan + block offset -> row_start
__global__ void k_scan_write() {
    __shared__ int sh[256];
    int t = threadIdx.x;
    int idx = blockIdx.x * 256 + t;
    int v = (idx < NN) ? g_deg[idx] - 1 : 0;
    sh[t] = v;
    __syncthreads();
    for (int o = 1; o < 256; o <<= 1) {
        int s = (t >= o) ? sh[t - o] : 0;
        __syncthreads();
        sh[t] += s;
        __syncthreads();
    }
    if (idx < NN) g_row_start[idx] = g_part[blockIdx.x] + sh[t] - v;
}

__global__ void k_csr_fill(const int* __restrict__ ei) {
    int e = blockIdx.x * blockDim.x + threadIdx.x;
    if (e >= EE) return;
    int r = __ldg(ei + e);
    int c = __ldg(ei + EE + e);
    int pos = g_row_start[c] + atomicAdd(&g_cnt[c], 1);
    g_csr_src[pos] = r;
    g_csr_w[pos] = __ldg(g_dis + r) * __ldg(g_dis + c);
}

// ============ register-tiled GEMM: 128x64 block tile, 8x4 thread tile ============
__device__ __forceinline__ void load_tile128(float* Xs, const float* __restrict__ src,
                                             int base, int tid) {
    for (int j = tid; j < 128 * 16; j += 256) {
        int gn = base + (j >> 4);
        float4 v = make_float4(0.f, 0.f, 0.f, 0.f);
        if (gn < NN) v = *reinterpret_cast<const float4*>(src + gn * 64 + (j & 15) * 4);
        *reinterpret_cast<float4*>(Xs + j * 4) = v;
    }
}

__device__ __forceinline__ void mm_accum8(const float* Xs, const float* Ws,
                                          int n0, int c0, float4 acc[8]) {
#pragma unroll
    for (int k = 0; k < 64; k += 4) {
        float4 wv0 = *reinterpret_cast<const float4*>(Ws + (k + 0) * 64 + c0);
        float4 wv1 = *reinterpret_cast<const float4*>(Ws + (k + 1) * 64 + c0);
        float4 wv2 = *reinterpret_cast<const float4*>(Ws + (k + 2) * 64 + c0);
        float4 wv3 = *reinterpret_cast<const float4*>(Ws + (k + 3) * 64 + c0);
#pragma unroll
        for (int i = 0; i < 8; i++) {
            float4 xv = *reinterpret_cast<const float4*>(Xs + (n0 + i) * 64 + k);
            acc[i].x += xv.x * wv0.x + xv.y * wv1.x + xv.z * wv2.x + xv.w * wv3.x;
            acc[i].y += xv.x * wv0.y + xv.y * wv1.y + xv.z * wv2.y + xv.w * wv3.y;
            acc[i].z += xv.x * wv0.z + xv.y * wv1.z + xv.z * wv2.z + xv.w * wv3.z;
            acc[i].w += xv.x * wv0.w + xv.y * wv1.w + xv.z * wv2.w + xv.w * wv3.w;
        }
    }
}

// ---------------- input projection ----------------
__global__ __launch_bounds__(256) void k_proj(const float* __restrict__ id_emb,
                                              const float* __restrict__ n2v_emb,
                                              const float* __restrict__ W,
                                              const float* __restrict__ b) {
    __shared__ float Xs[128 * 64];
    __shared__ float Ws[64 * 64];
    int tid = threadIdx.x;
    int base = blockIdx.x * 128;
    int c0 = (tid & 15) * 4, n0 = (tid >> 4) * 8;

    float4 acc[8];
#pragma unroll
    for (int i = 0; i < 8; i++) acc[i] = make_float4(0.f, 0.f, 0.f, 0.f);

#pragma unroll
    for (int chunk = 0; chunk < 2; chunk++) {
        load_tile128(Xs, chunk ? n2v_emb : id_emb, base, tid);
        const float* Wsrc = W + chunk * 64 * 64;
        for (int j = tid; j < 1024; j += 256)
            *reinterpret_cast<float4*>(Ws + j * 4) =
                *reinterpret_cast<const float4*>(Wsrc + j * 4);
        __syncthreads();
        mm_accum8(Xs, Ws, n0, c0, acc);
        __syncthreads();
    }

    float4 b4 = *reinterpret_cast<const float4*>(b + c0);
#pragma unroll
    for (int i = 0; i < 8; i++) {
        int gn = base + n0 + i;
        if (gn < NN) {
            float4 o = make_float4(acc[i].x + b4.x, acc[i].y + b4.y,
                                   acc[i].z + b4.z, acc[i].w + b4.w);
            *reinterpret_cast<float4*>(g_x + gn * 64 + c0) = o;
        }
    }
}

// ---------------- conv GEMM: h = x @ W (also zeroes BN stats) ----------------
__global__ __launch_bounds__(256) void k_conv(const float* __restrict__ W) {
    __shared__ float Xs[128 * 64];
    __shared__ float Ws[64 * 64];
    int tid = threadIdx.x;
    int base = blockIdx.x * 128;
    int c0 = (tid & 15) * 4, n0 = (tid >> 4) * 8;

    if (blockIdx.x == 0 && tid < 128) g_stats[tid] = 0.f;

    load_tile128(Xs, g_x, base, tid);
    for (int j = tid; j < 1024; j += 256)
        *reinterpret_cast<float4*>(Ws + j * 4) =
            *reinterpret_cast<const float4*>(W + j * 4);
    __syncthreads();

    float4 acc[8];
#pragma unroll
    for (int i = 0; i < 8; i++) acc[i] = make_float4(0.f, 0.f, 0.f, 0.f);
    mm_accum8(Xs, Ws, n0, c0, acc);

#pragma unroll
    for (int i = 0; i < 8; i++) {
        int gn = base + n0 + i;
        if (gn < NN)
            *reinterpret_cast<float4*>(g_h + gn * 64 + c0) = acc[i];
    }
}

// ---------------- CSR gather: warp per destination node, fused BN partial stats --
__global__ __launch_bounds__(256) void k_gather(const float* __restrict__ conv_b) {
    __shared__ float s_stats[128];
    int tid = threadIdx.x;
    if (tid < 128) s_stats[tid] = 0.f;
    __syncthreads();

    int warp = (blockIdx.x * blockDim.x + tid) >> 5;
    int lane = tid & 31;
    float2 acc = make_float2(0.f, 0.f);

    if (warp < NN) {
        int n = warp;
        int s0 = __ldg(g_row_start + n);
        int s1 = __ldg(g_row_start + n + 1);
        float d = __ldg(g_dis + n);
        float sl = d * d;                               // self-loop norm
        float2 h2 = *reinterpret_cast<const float2*>(g_h + n * 64 + lane * 2);
        float2 b2 = *reinterpret_cast<const float2*>(conv_b + lane * 2);
        acc.x = b2.x + h2.x * sl;
        acc.y = b2.y + h2.y * sl;

        int e = s0;
        for (; e + 1 < s1; e += 2) {                    // unroll 2 for MLP
            int   sa = __ldg(g_csr_src + e);
            float wa = __ldg(g_csr_w + e);
            int   sb = __ldg(g_csr_src + e + 1);
            float wb = __ldg(g_csr_w + e + 1);
            float2 ha = *reinterpret_cast<const float2*>(g_h + sa * 64 + lane * 2);
            float2 hb = *reinterpret_cast<const float2*>(g_h + sb * 64 + lane * 2);
            acc.x += wa * ha.x + wb * hb.x;
            acc.y += wa * ha.y + wb * hb.y;
        }
        if (e < s1) {
            int   sa = __ldg(g_csr_src + e);
            float wa = __ldg(g_csr_w + e);
            float2 ha = *reinterpret_cast<const float2*>(g_h + sa * 64 + lane * 2);
            acc.x += wa * ha.x;
            acc.y += wa * ha.y;
        }
        *reinterpret_cast<float2*>(g_agg + n * 64 + lane * 2) = acc;
    }

    // block-local BN stats
    atomicAdd(&s_stats[2 * lane],          acc.x);
    atomicAdd(&s_stats[2 * lane + 1],      acc.y);
    atomicAdd(&s_stats[64 + 2 * lane],     acc.x * acc.x);
    atomicAdd(&s_stats[64 + 2 * lane + 1], acc.y * acc.y);
    __syncthreads();
    if (tid < 128) atomicAdd(&g_stats[tid], s_stats[tid]);
}

// ---------------- BN finalize + apply + residual relu (fused) ----------------
__global__ void k_bn_apply(const float* __restrict__ gamma,
                           const float* __restrict__ beta) {
    __shared__ float sc[64], sf[64];
    int tid = threadIdx.x;
    if (tid < 64) {
        float mu  = g_stats[tid] * (1.0f / NN);
        float var = g_stats[64 + tid] * (1.0f / NN) - mu * mu;
        float inv = rsqrtf(var + BN_EPS);
        float gm  = gamma[tid];
        sc[tid] = gm * inv;
        sf[tid] = beta[tid] - mu * inv * gm;
    }
    __syncthreads();
    int i = blockIdx.x * blockDim.x + tid;          // float4 index
    if (i < NN * 16) {
        int c0 = (i & 15) * 4;
        float4 v = reinterpret_cast<const float4*>(g_agg)[i];
        float4 x = reinterpret_cast<const float4*>(g_x)[i];
        x.x += fmaxf(v.x * sc[c0 + 0] + sf[c0 + 0], 0.f);
        x.y += fmaxf(v.y * sc[c0 + 1] + sf[c0 + 1], 0.f);
        x.z += fmaxf(v.z * sc[c0 + 2] + sf[c0 + 2], 0.f);
        x.w += fmaxf(v.w * sc[c0 + 3] + sf[c0 + 3], 0.f);
        reinterpret_cast<float4*>(g_x)[i] = x;
    }
}

// ---------------- link decoder ----------------
__global__ void k_decode(const int* __restrict__ pe, float* __restrict__ out) {
    int w = (blockIdx.x * blockDim.x + threadIdx.x) >> 5;
    int lane = threadIdx.x & 31;
    if (w >= EP) return;
    int a = __ldg(pe + 2 * w);
    int b = __ldg(pe + 2 * w + 1);
    float2 za = __ldg(reinterpret_cast<const float2*>(g_x + a * 64) + lane);
    float2 zb = __ldg(reinterpret_cast<const float2*>(g_x + b * 64) + lane);
    float s = za.x * zb.x + za.y * zb.y;
#pragma unroll
    for (int o = 16; o; o >>= 1) s += __shfl_xor_sync(0xffffffffu, s, o);
    if (lane == 0) out[w] = s;
}

// ---------------- launch ----------------
extern "C" void kernel_launch(void* const* d_in, const int* in_sizes, int n_in,
                              void* d_out, int out_size) {
    const int*   edge_index = (const int*)d_in[0];
    const int*   pred_edge  = (const int*)d_in[1];
    const float* id_emb     = (const float*)d_in[2];
    const float* n2v_emb    = (const float*)d_in[3];
    const float* proj_w     = (const float*)d_in[4];
    const float* proj_b     = (const float*)d_in[5];
    const float* conv_w     = (const float*)d_in[6];
    const float* conv_b     = (const float*)d_in[7];
    const float* bn_gamma   = (const float*)d_in[8];
    const float* bn_beta    = (const float*)d_in[9];
    float*       out        = (float*)d_out;

    const int TB = 256;
    const int GBLK = (NN + 127) / 128;

    // CSR build (reused across both layers)
    k_init      <<<(NN + TB - 1) / TB, TB>>>();
    k_deg_count <<<(EE + TB - 1) / TB, TB>>>(edge_index);
    k_dis       <<<(NN + TB - 1) / TB, TB>>>();
    k_scan_part <<<NB_SCAN, TB>>>();
    k_scan_mid  <<<1, TB>>>();
    k_scan_write<<<NB_SCAN, TB>>>();
    k_csr_fill  <<<(EE + TB - 1) / TB, TB>>>(edge_index);

    k_proj<<<GBLK, TB>>>(id_emb, n2v_emb, proj_w, proj_b);

    for (int l = 0; l < LYR; l++) {
        k_conv    <<<GBLK, TB>>>(conv_w + l * HID * HID);
        k_gather  <<<(NN * 32 + TB - 1) / TB, TB>>>(conv_b + l * HID);
        k_bn_apply<<<(NN * 16 + TB - 1) / TB, TB>>>(bn_gamma + l * HID, bn_beta + l * HID);
    }

    k_decode<<<(EP * 32 + TB - 1) / TB, TB>>>(pred_edge, out);
}